// round 7
// baseline (speedup 1.0000x reference)
#include <cuda_runtime.h>
#include <cuda_bf16.h>
#include <stdint.h>

// SlidingWindowMatrixMult3D via mma.sync bf16, 3-pass fp32 emulation.
// Z[b,w,t] = sum_c Q[b,w,c]*K[b,w+t,c] + sum_c Q[b,w,c]*bias[c,t]
// B=16, T=1024, C=128.
//
// R7: fused band+bias per sub-tile. CTA strip = 64 w-rows x 256 t-cols
// (4 sub-tiles 64x64). Smem: Q + 3x64-row K chunk ring + double-buffered
// bias tile + bias staging (221 KB, 1 CTA/SM). Warp specialization:
// 4 band warps (m32 x n48) + 4 bias warps (m32 x n32), SMSP-balanced.
// Epilogue: bias warps stage P to smem; band warps write Z = band + P once.

#define Bz 16
#define Tz 1024
#define Cz 128
#define KTOT 2047
#define KPADROWS 128

// ---- global bf16 scratch ----
__device__ __nv_bfloat16 g_Qh[Bz * Tz * Cz];
__device__ __nv_bfloat16 g_Ql[Bz * Tz * Cz];
__device__ __nv_bfloat16 g_Kh[(Bz * KTOT + KPADROWS) * Cz];
__device__ __nv_bfloat16 g_Kl[(Bz * KTOT + KPADROWS) * Cz];
__device__ __nv_bfloat16 g_Bh[Tz * Cz];     // transposed: [t][c]
__device__ __nv_bfloat16 g_Bl[Tz * Cz];

// ---- smem layout: bf16 rows (128 cols) padded to 272 B ----
#define RST 272u
#define TSZ 17408u           // one 64-row half-tile (hi or lo)
#define OFF_QH 0u            // Q hi 17408, Q lo at +TSZ
#define OFF_K  34816u        // 3 slots x (hi+lo) = 3 x 34816
#define KSLOT  34816u
#define OFF_BIAS 139264u     // 2 bufs x 34816
#define OFF_ZST  208896u     // 64 rows x 272 B fp32 staging (stride 68 floats)
#define SMEM_BYTES 226304u

// ---------------------------------------------------------------------------
__device__ __forceinline__ uint32_t cvta_sh(const void* p) {
    uint32_t a;
    asm("{ .reg .u64 t; cvta.to.shared.u64 t, %1; cvt.u32.u64 %0, t; }"
        : "=r"(a) : "l"(p));
    return a;
}
__device__ __forceinline__ void cp16(uint32_t d, const void* s) {
    asm volatile("cp.async.ca.shared.global [%0], [%1], 16;" :: "r"(d), "l"(s));
}
#define CP_WAIT_ALL() asm volatile("cp.async.wait_all;" ::: "memory")

__device__ __forceinline__ void ldsm4(uint32_t* r, uint32_t a) {
    asm volatile("ldmatrix.sync.aligned.m8n8.x4.shared.b16 {%0,%1,%2,%3}, [%4];"
                 : "=r"(r[0]), "=r"(r[1]), "=r"(r[2]), "=r"(r[3]) : "r"(a));
}
__device__ __forceinline__ void mma_bf16(float* d, const uint32_t* a,
                                         uint32_t b0, uint32_t b1) {
    asm volatile(
        "mma.sync.aligned.m16n8k16.row.col.f32.bf16.bf16.f32 "
        "{%0,%1,%2,%3}, {%4,%5,%6,%7}, {%8,%9}, {%0,%1,%2,%3};"
        : "+f"(d[0]), "+f"(d[1]), "+f"(d[2]), "+f"(d[3])
        : "r"(a[0]), "r"(a[1]), "r"(a[2]), "r"(a[3]), "r"(b0), "r"(b1));
}
__device__ __forceinline__ void mma3(float* d, const uint32_t* ah, const uint32_t* al,
                                     uint32_t bh0, uint32_t bh1,
                                     uint32_t bl0, uint32_t bl1) {
    mma_bf16(d, ah, bh0, bh1);
    mma_bf16(d, al, bh0, bh1);
    mma_bf16(d, ah, bl0, bl1);
}

// ---------------------------------------------------------------------------
// merged pre-pass: Q, K (float4 path) + bias transpose
__global__ void conv_all_kernel(const float* __restrict__ Q,
                                const float* __restrict__ K,
                                const float* __restrict__ bias)
{
    const int nQ = Bz * Tz * Cz / 4;        // 524288
    const int nK = Bz * KTOT * Cz / 4;      // 1048064
    const int nB = Tz * Cz / 4;             // 32768
    int i = blockIdx.x * blockDim.x + threadIdx.x;
    if (i < nQ + nK) {
        const float4* src;
        uint2 *dh, *dl;
        int j;
        if (i < nQ) { src = (const float4*)Q; dh = (uint2*)g_Qh; dl = (uint2*)g_Ql; j = i; }
        else        { src = (const float4*)K; dh = (uint2*)g_Kh; dl = (uint2*)g_Kl; j = i - nQ; }
        float4 v = __ldg(src + j);
        __nv_bfloat162 h01 = __floats2bfloat162_rn(v.x, v.y);
        __nv_bfloat162 h23 = __floats2bfloat162_rn(v.z, v.w);
        float2 f01 = __bfloat1622float2(h01);
        float2 f23 = __bfloat1622float2(h23);
        __nv_bfloat162 l01 = __floats2bfloat162_rn(v.x - f01.x, v.y - f01.y);
        __nv_bfloat162 l23 = __floats2bfloat162_rn(v.z - f23.x, v.w - f23.y);
        uint2 h, l;
        h.x = *(uint32_t*)&h01; h.y = *(uint32_t*)&h23;
        l.x = *(uint32_t*)&l01; l.y = *(uint32_t*)&l23;
        dh[j] = h;
        dl[j] = l;
    } else if (i < nQ + nK + nB) {
        int u = i - nQ - nK;
        int o = u * 4;
        int t = o >> 7, c = o & 127;
        float4 v;
        v.x = __ldg(bias + (c + 0) * Tz + t);
        v.y = __ldg(bias + (c + 1) * Tz + t);
        v.z = __ldg(bias + (c + 2) * Tz + t);
        v.w = __ldg(bias + (c + 3) * Tz + t);
        __nv_bfloat162 h01 = __floats2bfloat162_rn(v.x, v.y);
        __nv_bfloat162 h23 = __floats2bfloat162_rn(v.z, v.w);
        float2 f01 = __bfloat1622float2(h01);
        float2 f23 = __bfloat1622float2(h23);
        __nv_bfloat162 l01 = __floats2bfloat162_rn(v.x - f01.x, v.y - f01.y);
        __nv_bfloat162 l23 = __floats2bfloat162_rn(v.z - f23.x, v.w - f23.y);
        uint2 h, l;
        h.x = *(uint32_t*)&h01; h.y = *(uint32_t*)&h23;
        l.x = *(uint32_t*)&l01; l.y = *(uint32_t*)&l23;
        ((uint2*)g_Bh)[u] = h;
        ((uint2*)g_Bl)[u] = l;
    }
}

// ---------------------------------------------------------------------------
__global__ void __launch_bounds__(256, 1)
swmm3d_main(float* __restrict__ Z)
{
    extern __shared__ char sm[];
    const uint32_t sb = cvta_sh(sm);

    const int tid  = threadIdx.x;
    const int wid  = tid >> 5;
    const int lane = tid & 31;
    const int lr = lane >> 2;
    const int lc = (lane & 3) * 2;
    const int m8 = lane >> 3, mr = lane & 7;

    const int b  = blockIdx.x >> 4;
    const int w0 = (blockIdx.x & 15) * 64;
    const int t0 = blockIdx.y * 256;
    const int kbase = w0 + t0;

    // roles: band warps {0,1,6,7}, bias warps {2,3,4,5}; rg = row group
    const bool band = (wid < 2) || (wid > 5);
    const int rg  = wid >> 2;
    const int sub = wid & 1;      // band: which n-half; bias: which col-half

    // ---- prologue: Q, K chunks 0,1, bias buf 0 ----
    const char* gq_h = (const char*)g_Qh + (size_t)(b * Tz + w0) * 256;
    const char* gq_l = (const char*)g_Ql + (size_t)(b * Tz + w0) * 256;
    const char* gk_h = (const char*)g_Kh + (size_t)(b * KTOT + kbase) * 256;
    const char* gk_l = (const char*)g_Kl + (size_t)(b * KTOT + kbase) * 256;
    const char* gb_h = (const char*)g_Bh + (size_t)t0 * 256;
    const char* gb_l = (const char*)g_Bl + (size_t)t0 * 256;

    for (int i = tid; i < 64 * 16; i += 256) {
        int r = i >> 4, c = i & 15;
        uint32_t so = (uint32_t)r * RST + c * 16;
        size_t go = (size_t)r * 256 + c * 16;
        cp16(sb + OFF_QH + so, gq_h + go);
        cp16(sb + OFF_QH + TSZ + so, gq_l + go);
        cp16(sb + OFF_BIAS + so, gb_h + go);
        cp16(sb + OFF_BIAS + TSZ + so, gb_l + go);
    }
    for (int ch = 0; ch < 2; ch++)
        for (int i = tid; i < 64 * 16; i += 256) {
            int r = i >> 4, c = i & 15;
            uint32_t so = OFF_K + ch * KSLOT + (uint32_t)r * RST + c * 16;
            size_t go = (size_t)(ch * 64 + r) * 256 + c * 16;
            cp16(sb + so, gk_h + go);
            cp16(sb + so + TSZ, gk_l + go);
        }

    // A addresses (two m16 tiles per warp)
    const uint32_t aH0 = sb + OFF_QH + (uint32_t)(32 * rg + ((m8 & 1) << 3) + mr) * RST
                       + (m8 >> 1) * 16;
    const uint32_t aH1 = aH0 + 16 * RST;

    const int nB = ((m8 >> 1) << 3) + mr;   // B n-offset within an n16 pair
    const uint32_t cBy = (m8 & 1) * 16;     // B k-halves byte offset

    float* ZST = (float*)(sm + OFF_ZST);    // [64][68] fp32 staging
    float* __restrict__ Zrow0 = Z + ((size_t)(b * Tz + w0)) * Tz + t0;

    #pragma unroll 1
    for (int j = 0; j < 4; j++) {
        const int wb = 64 * j;
        CP_WAIT_ALL();
        __syncthreads();

        // ---- prefetch next K chunk + bias tile (overlaps MMA) ----
        if (j < 3) {
            int slot = j + 2;
            if (slot >= 3) slot -= 3;
            for (int i = tid; i < 64 * 16; i += 256) {
                int r = i >> 4, c = i & 15;
                uint32_t so = OFF_K + (uint32_t)slot * KSLOT + (uint32_t)r * RST + c * 16;
                size_t go = (size_t)((j + 2) * 64 + r) * 256 + c * 16;
                cp16(sb + so, gk_h + go);
                cp16(sb + so + TSZ, gk_l + go);
            }
            for (int i = tid; i < 64 * 16; i += 256) {
                int r = i >> 4, c = i & 15;
                uint32_t so = OFF_BIAS + (uint32_t)((j + 1) & 1) * KSLOT
                            + (uint32_t)r * RST + c * 16;
                size_t go = (size_t)((j + 1) * 64 + r) * 256 + c * 16;
                cp16(sb + so, gb_h + go);
                cp16(sb + so + TSZ, gb_l + go);
            }
        }

        if (band) {
            // ---- band warp: 3 n16 pairs starting at n8 index s8 ----
            const int s8 = 4 * rg + 6 * sub;
            uint32_t bA[3];
            #pragma unroll
            for (int p = 0; p < 3; p++) {
                int rel = wb + (s8 + 2 * p) * 8 + nB;  // K row rel to kbase
                int c = rel >> 6;
                int cs = c - ((c >= 3) ? 3 : 0);
                bA[p] = sb + OFF_K + (uint32_t)cs * KSLOT + (uint32_t)(rel & 63) * RST + cBy;
            }
            float acc[3][2][2][4];
            #pragma unroll
            for (int p = 0; p < 3; p++)
                #pragma unroll
                for (int nh = 0; nh < 2; nh++)
                    #pragma unroll
                    for (int mh = 0; mh < 2; mh++)
                        #pragma unroll
                        for (int e = 0; e < 4; e++) acc[p][nh][mh][e] = 0.0f;

            #pragma unroll 1
            for (int kt = 0; kt < 8; kt++) {
                uint32_t ah0[4], ah1[4], al0[4], al1[4];
                ldsm4(ah0, aH0 + kt * 32);
                ldsm4(ah1, aH1 + kt * 32);
                ldsm4(al0, aH0 + TSZ + kt * 32);
                ldsm4(al1, aH1 + TSZ + kt * 32);
                #pragma unroll
                for (int p = 0; p < 3; p++) {
                    uint32_t bh[4], bl[4];
                    ldsm4(bh, bA[p] + kt * 32);
                    ldsm4(bl, bA[p] + TSZ + kt * 32);
                    mma3(acc[p][0][0], ah0, al0, bh[0], bh[1], bl[0], bl[1]);
                    mma3(acc[p][0][1], ah1, al1, bh[0], bh[1], bl[0], bl[1]);
                    mma3(acc[p][1][0], ah0, al0, bh[2], bh[3], bl[2], bl[3]);
                    mma3(acc[p][1][1], ah1, al1, bh[2], bh[3], bl[2], bl[3]);
                }
            }
            __syncthreads();   // bias staging complete

            // ---- Z = band + staged bias, single write ----
            #pragma unroll
            for (int p = 0; p < 3; p++)
                #pragma unroll
                for (int nh = 0; nh < 2; nh++) {
                    const int n0 = (s8 + 2 * p + nh) * 8 + lc;
                    #pragma unroll
                    for (int mh = 0; mh < 2; mh++)
                        #pragma unroll
                        for (int hh = 0; hh < 2; hh++) {
                            const int r = 32 * rg + 16 * mh + 8 * hh + lr;
                            const int jj = n0 - r;
                            float* zp = Zrow0 + (size_t)r * Tz + wb;
                            if ((unsigned)jj < 64u)
                                zp[jj] = acc[p][nh][mh][2 * hh] + ZST[r * 68 + jj];
                            if ((unsigned)(jj + 1) < 64u)
                                zp[jj + 1] = acc[p][nh][mh][2 * hh + 1] + ZST[r * 68 + jj + 1];
                        }
                }
        } else {
            // ---- bias warp: 2 n16 pairs at n8 index 4*sub ----
            const int s8b = 4 * sub;
            uint32_t bA[2];
            #pragma unroll
            for (int p = 0; p < 2; p++) {
                int trow = (s8b + 2 * p) * 8 + nB;
                bA[p] = sb + OFF_BIAS + (uint32_t)(j & 1) * KSLOT
                      + (uint32_t)trow * RST + cBy;
            }
            float acc[2][2][2][4];
            #pragma unroll
            for (int p = 0; p < 2; p++)
                #pragma unroll
                for (int nh = 0; nh < 2; nh++)
                    #pragma unroll
                    for (int mh = 0; mh < 2; mh++)
                        #pragma unroll
                        for (int e = 0; e < 4; e++) acc[p][nh][mh][e] = 0.0f;

            #pragma unroll 1
            for (int kt = 0; kt < 8; kt++) {
                uint32_t ah0[4], ah1[4], al0[4], al1[4];
                ldsm4(ah0, aH0 + kt * 32);
                ldsm4(ah1, aH1 + kt * 32);
                ldsm4(al0, aH0 + TSZ + kt * 32);
                ldsm4(al1, aH1 + TSZ + kt * 32);
                #pragma unroll
                for (int p = 0; p < 2; p++) {
                    uint32_t bh[4], bl[4];
                    ldsm4(bh, bA[p] + kt * 32);
                    ldsm4(bl, bA[p] + TSZ + kt * 32);
                    mma3(acc[p][0][0], ah0, al0, bh[0], bh[1], bl[0], bl[1]);
                    mma3(acc[p][0][1], ah1, al1, bh[0], bh[1], bl[0], bl[1]);
                    mma3(acc[p][1][0], ah0, al0, bh[2], bh[3], bl[2], bl[3]);
                    mma3(acc[p][1][1], ah1, al1, bh[2], bh[3], bl[2], bl[3]);
                }
            }
            // ---- stage P into ZST ----
            #pragma unroll
            for (int p = 0; p < 2; p++)
                #pragma unroll
                for (int nh = 0; nh < 2; nh++) {
                    const int cj = (s8b + 2 * p + nh) * 8 + lc;
                    #pragma unroll
                    for (int mh = 0; mh < 2; mh++)
                        #pragma unroll
                        for (int hh = 0; hh < 2; hh++) {
                            const int r = 32 * rg + 16 * mh + 8 * hh + lr;
                            float2 v;
                            v.x = acc[p][nh][mh][2 * hh];
                            v.y = acc[p][nh][mh][2 * hh + 1];
                            *(float2*)&ZST[r * 68 + cj] = v;
                        }
                }
            __syncthreads();   // matches band warps' post-MMA barrier
            // band warps write Z; bias warps proceed to next sub-tile top
        }
    }
}

// ---------------------------------------------------------------------------
extern "C" void kernel_launch(void* const* d_in, const int* in_sizes, int n_in,
                              void* d_out, int out_size)
{
    const float* Q    = (const float*)d_in[0];   // (16, 1024, 128)
    const float* K    = (const float*)d_in[1];   // (16, 2047, 128)
    const float* bias = (const float*)d_in[2];   // (128, 1024)
    float* Z = (float*)d_out;                    // (16, 1024, 1024)

    static int configured = 0;
    if (!configured) {
        cudaFuncSetAttribute(swmm3d_main,
                             cudaFuncAttributeMaxDynamicSharedMemorySize, SMEM_BYTES);
        configured = 1;
    }

    conv_all_kernel<<<6270, 256>>>(Q, K, bias);

    dim3 grid(256, 4, 1);   // x = b*16 + w-strip, y = t-strip
    swmm3d_main<<<grid, 256, SMEM_BYTES>>>(Z);
}

// round 8
// speedup vs baseline: 1.3431x; 1.3431x over previous
#include <cuda_runtime.h>
#include <cuda_bf16.h>
#include <stdint.h>

// SlidingWindowMatrixMult3D via mma.sync bf16, 3-pass fp32 emulation.
// Z[b,w,t] = sum_c Q[b,w,c]*K[b,w+t,c] + sum_c Q[b,w,c]*bias[c,t]
// B=16, T=1024, C=128.
//
// R8: two specialized kernels after the conv pre-pass:
//   1. band kernel (R6 strip kernel minus bias phases): 64w x 256t strips,
//      sliding 128-row K ring, m16 warp tiles, pure Z stores. 2 CTA/SM.
//   2. bias GEMM kernel: Z += Q @ bias^T, 64x128 tiles, m32n32 warps,
//      K=128 smem-resident, RMW epilogue. 2 CTA/SM.

#define Bz 16
#define Tz 1024
#define Cz 128
#define KTOT 2047
#define KPADROWS 128

// ---- global bf16 scratch ----
__device__ __nv_bfloat16 g_Qh[Bz * Tz * Cz];
__device__ __nv_bfloat16 g_Ql[Bz * Tz * Cz];
__device__ __nv_bfloat16 g_Kh[(Bz * KTOT + KPADROWS) * Cz];
__device__ __nv_bfloat16 g_Kl[(Bz * KTOT + KPADROWS) * Cz];
__device__ __nv_bfloat16 g_Bh[Tz * Cz];     // transposed: [t][c]
__device__ __nv_bfloat16 g_Bl[Tz * Cz];

// ---- shared layouts (both kernels 102 KB -> 2 CTA/SM) ----
#define RST 272u
// band kernel
#define OFF_QH 0u
#define OFF_QL 17408u
#define OFF_KH 34816u            // 128-slot ring (hi)
#define OFF_KL 69632u            // 128-slot ring (lo)
#define DHL    34816u            // hi -> lo delta
#define SMEM_BAND 104448u
// bias kernel
#define BO_QH 0u
#define BO_QL 17408u
#define BO_BH 34816u             // 128 bias rows (hi)
#define BO_BL 69632u
#define SMEM_BIAS 104448u

// ---------------------------------------------------------------------------
__device__ __forceinline__ uint32_t cvta_sh(const void* p) {
    uint32_t a;
    asm("{ .reg .u64 t; cvta.to.shared.u64 t, %1; cvt.u32.u64 %0, t; }"
        : "=r"(a) : "l"(p));
    return a;
}
__device__ __forceinline__ void cp16(uint32_t d, const void* s) {
    asm volatile("cp.async.ca.shared.global [%0], [%1], 16;" :: "r"(d), "l"(s));
}
#define CP_WAIT_ALL() asm volatile("cp.async.wait_all;" ::: "memory")

__device__ __forceinline__ void ldsm4(uint32_t* r, uint32_t a) {
    asm volatile("ldmatrix.sync.aligned.m8n8.x4.shared.b16 {%0,%1,%2,%3}, [%4];"
                 : "=r"(r[0]), "=r"(r[1]), "=r"(r[2]), "=r"(r[3]) : "r"(a));
}
__device__ __forceinline__ void ldsm2(uint32_t* r, uint32_t a) {
    asm volatile("ldmatrix.sync.aligned.m8n8.x2.shared.b16 {%0,%1}, [%2];"
                 : "=r"(r[0]), "=r"(r[1]) : "r"(a));
}
__device__ __forceinline__ void mma_bf16(float* d, const uint32_t* a,
                                         uint32_t b0, uint32_t b1) {
    asm volatile(
        "mma.sync.aligned.m16n8k16.row.col.f32.bf16.bf16.f32 "
        "{%0,%1,%2,%3}, {%4,%5,%6,%7}, {%8,%9}, {%0,%1,%2,%3};"
        : "+f"(d[0]), "+f"(d[1]), "+f"(d[2]), "+f"(d[3])
        : "r"(a[0]), "r"(a[1]), "r"(a[2]), "r"(a[3]), "r"(b0), "r"(b1));
}
__device__ __forceinline__ void mma3(float* d, const uint32_t* ah, const uint32_t* al,
                                     uint32_t bh0, uint32_t bh1,
                                     uint32_t bl0, uint32_t bl1) {
    mma_bf16(d, ah, bh0, bh1);
    mma_bf16(d, al, bh0, bh1);
    mma_bf16(d, ah, bl0, bl1);
}

// ---------------------------------------------------------------------------
// pre-pass: Q, K (float4 path) + bias transpose
__global__ void conv_all_kernel(const float* __restrict__ Q,
                                const float* __restrict__ K,
                                const float* __restrict__ bias)
{
    const int nQ = Bz * Tz * Cz / 4;        // 524288
    const int nK = Bz * KTOT * Cz / 4;      // 1048064
    const int nB = Tz * Cz / 4;             // 32768
    int i = blockIdx.x * blockDim.x + threadIdx.x;
    if (i < nQ + nK) {
        const float4* src;
        uint2 *dh, *dl;
        int j;
        if (i < nQ) { src = (const float4*)Q; dh = (uint2*)g_Qh; dl = (uint2*)g_Ql; j = i; }
        else        { src = (const float4*)K; dh = (uint2*)g_Kh; dl = (uint2*)g_Kl; j = i - nQ; }
        float4 v = __ldg(src + j);
        __nv_bfloat162 h01 = __floats2bfloat162_rn(v.x, v.y);
        __nv_bfloat162 h23 = __floats2bfloat162_rn(v.z, v.w);
        float2 f01 = __bfloat1622float2(h01);
        float2 f23 = __bfloat1622float2(h23);
        __nv_bfloat162 l01 = __floats2bfloat162_rn(v.x - f01.x, v.y - f01.y);
        __nv_bfloat162 l23 = __floats2bfloat162_rn(v.z - f23.x, v.w - f23.y);
        uint2 h, l;
        h.x = *(uint32_t*)&h01; h.y = *(uint32_t*)&h23;
        l.x = *(uint32_t*)&l01; l.y = *(uint32_t*)&l23;
        dh[j] = h;
        dl[j] = l;
    } else if (i < nQ + nK + nB) {
        int u = i - nQ - nK;
        int o = u * 4;
        int t = o >> 7, c = o & 127;
        float4 v;
        v.x = __ldg(bias + (c + 0) * Tz + t);
        v.y = __ldg(bias + (c + 1) * Tz + t);
        v.z = __ldg(bias + (c + 2) * Tz + t);
        v.w = __ldg(bias + (c + 3) * Tz + t);
        __nv_bfloat162 h01 = __floats2bfloat162_rn(v.x, v.y);
        __nv_bfloat162 h23 = __floats2bfloat162_rn(v.z, v.w);
        float2 f01 = __bfloat1622float2(h01);
        float2 f23 = __bfloat1622float2(h23);
        __nv_bfloat162 l01 = __floats2bfloat162_rn(v.x - f01.x, v.y - f01.y);
        __nv_bfloat162 l23 = __floats2bfloat162_rn(v.z - f23.x, v.w - f23.y);
        uint2 h, l;
        h.x = *(uint32_t*)&h01; h.y = *(uint32_t*)&h23;
        l.x = *(uint32_t*)&l01; l.y = *(uint32_t*)&l23;
        ((uint2*)g_Bh)[u] = h;
        ((uint2*)g_Bl)[u] = l;
    }
}

// ---------------------------------------------------------------------------
// Kernel 1: band term. 64w x 256t strips, sliding K ring, pure Z stores.
__global__ void __launch_bounds__(256, 2)
band_kernel(float* __restrict__ Z)
{
    extern __shared__ char sm[];
    const uint32_t sb = cvta_sh(sm);

    const int tid  = threadIdx.x;
    const int wid  = tid >> 5;
    const int lane = tid & 31;
    const int lr = lane >> 2;
    const int lc = (lane & 3) * 2;
    const int mt = wid >> 1;          // rows 16*mt .. 16*mt+15
    const int s  = wid & 1;

    const int b  = blockIdx.x >> 4;
    const int w0 = (blockIdx.x & 15) * 64;
    const int t0 = blockIdx.y * 256;
    const int kbase = w0 + t0;

    // ---- prologue: Q (64 rows), K ring rel rows [0,126] ----
    const char* gq_h = (const char*)g_Qh + (size_t)(b * Tz + w0) * 256;
    const char* gq_l = (const char*)g_Ql + (size_t)(b * Tz + w0) * 256;
    const char* gk_h = (const char*)g_Kh + (size_t)(b * KTOT + kbase) * 256;
    const char* gk_l = (const char*)g_Kl + (size_t)(b * KTOT + kbase) * 256;

    for (int i = tid; i < 64 * 16; i += 256) {
        int r = i >> 4, c = i & 15;
        uint32_t so = (uint32_t)r * RST + c * 16;
        size_t go = (size_t)r * 256 + c * 16;
        cp16(sb + OFF_QH + so, gq_h + go);
        cp16(sb + OFF_QL + so, gq_l + go);
    }
    for (int i = tid; i < 127 * 16; i += 256) {
        int r = i >> 4, c = i & 15;
        uint32_t so = (uint32_t)r * RST + c * 16;
        size_t go = (size_t)r * 256 + c * 16;
        cp16(sb + OFF_KH + so, gk_h + go);
        cp16(sb + OFF_KL + so, gk_l + go);
    }

    // ldmatrix lane components
    const uint32_t m8 = lane >> 3, mr = lane & 7;
    const uint32_t a_row = 16u * mt + ((m8 & 1) << 3) + mr;
    const uint32_t aH = sb + OFF_QH + a_row * RST + (m8 >> 1) * 16;
    const uint32_t aL = aH + (OFF_QL - OFF_QH);
    const int rB  = (int)((m8 >> 1) * 8 + mr);   // B n-row within ldsm4 group
    const uint32_t cB = (m8 & 1) * 16;
    const uint32_t l16 = lane & 15;
    const int rB2 = (int)(l16 & 7);
    const uint32_t cB2 = (l16 >> 3) * 16;

    const int gnt0 = 2 * mt + 5 * s;             // band n-tile base (per warp)

    #pragma unroll 1
    for (int j = 0; j < 4; j++) {
        const int wb = 64 * j;
        float* __restrict__ Zb = Z + ((size_t)b * Tz + w0) * Tz + t0 + wb;

        CP_WAIT_ALL();
        __syncthreads();                         // K window ready

        // ---- band MMA: 5 n-tiles ----
        float acc[5][4];
        #pragma unroll
        for (int u = 0; u < 5; u++)
            #pragma unroll
            for (int e = 0; e < 4; e++) acc[u][e] = 0.0f;

        uint32_t bb0 = sb + OFF_KH + (uint32_t)((wb + gnt0 * 8 + rB) & 127) * RST + cB;
        uint32_t bb1 = sb + OFF_KH + (uint32_t)((wb + (gnt0 + 2) * 8 + rB) & 127) * RST + cB;
        uint32_t bb2 = sb + OFF_KH + (uint32_t)((wb + (gnt0 + 4) * 8 + rB2) & 127) * RST + cB2;

        #pragma unroll 1
        for (int kt = 0; kt < 8; kt++) {
            uint32_t ah[4], al[4];
            ldsm4(ah, aH + kt * 32);
            ldsm4(al, aL + kt * 32);
            uint32_t bh[4], bl[4];
            ldsm4(bh, bb0 + kt * 32);
            ldsm4(bl, bb0 + DHL + kt * 32);
            mma3(acc[0], ah, al, bh[0], bh[1], bl[0], bl[1]);
            mma3(acc[1], ah, al, bh[2], bh[3], bl[2], bl[3]);
            ldsm4(bh, bb1 + kt * 32);
            ldsm4(bl, bb1 + DHL + kt * 32);
            mma3(acc[2], ah, al, bh[0], bh[1], bl[0], bl[1]);
            mma3(acc[3], ah, al, bh[2], bh[3], bl[2], bl[3]);
            uint32_t b2h[2], b2l[2];
            ldsm2(b2h, bb2 + kt * 32);
            ldsm2(b2l, bb2 + DHL + kt * 32);
            mma3(acc[4], ah, al, b2h[0], b2h[1], b2l[0], b2l[1]);
        }
        __syncthreads();                         // all ring reads complete

        // ---- prefetch next 64 K rows (rel [wb+127, wb+190]) ----
        if (j < 3) {
            for (int i = tid; i < 64 * 16; i += 256) {
                int r = i >> 4, c = i & 15;
                int rel = wb + 127 + r;
                uint32_t so = (uint32_t)(rel & 127) * RST + c * 16;
                size_t go = (size_t)rel * 256 + c * 16;
                cp16(sb + OFF_KH + so, gk_h + go);
                cp16(sb + OFF_KL + so, gk_l + go);
            }
        }

        // ---- scatter band sheared to Z (pure store; overlaps prefetch) ----
        #pragma unroll
        for (int u = 0; u < 5; u++) {
            const int n0 = (gnt0 + u) * 8 + lc;
            #pragma unroll
            for (int h = 0; h < 2; h++) {
                const int row = 16 * mt + lr + 8 * h;
                const int j0 = n0 - row;
                if ((unsigned)j0 < 64u)       Zb[(size_t)row * Tz + j0]     = acc[u][2 * h];
                if ((unsigned)(j0 + 1) < 64u) Zb[(size_t)row * Tz + j0 + 1] = acc[u][2 * h + 1];
            }
        }
    }
}

// ---------------------------------------------------------------------------
// Kernel 2: bias GEMM, Z += Q @ bias^T. 64m x 128n tiles, m32n32 warps.
__global__ void __launch_bounds__(256, 2)
bias_kernel(float* __restrict__ Z)
{
    extern __shared__ char sm[];
    const uint32_t sb = cvta_sh(sm);

    const int tid  = threadIdx.x;
    const int wid  = tid >> 5;
    const int lane = tid & 31;
    const int lr = lane >> 2;
    const int lc = (lane & 3) * 2;
    const int rg = wid & 1;           // rows 32*rg .. 32*rg+31
    const int nq = wid >> 1;          // cols 32*nq .. 32*nq+31

    const int m0 = blockIdx.x * 64;   // global row (= b*1024 + w)
    const int n0 = blockIdx.y * 128;

    // ---- load Q (64 rows) + bias (128 rows) ----
    const char* gq_h = (const char*)g_Qh + (size_t)m0 * 256;
    const char* gq_l = (const char*)g_Ql + (size_t)m0 * 256;
    const char* gb_h = (const char*)g_Bh + (size_t)n0 * 256;
    const char* gb_l = (const char*)g_Bl + (size_t)n0 * 256;

    for (int i = tid; i < 64 * 16; i += 256) {
        int r = i >> 4, c = i & 15;
        uint32_t so = (uint32_t)r * RST + c * 16;
        size_t go = (size_t)r * 256 + c * 16;
        cp16(sb + BO_QH + so, gq_h + go);
        cp16(sb + BO_QL + so, gq_l + go);
    }
    for (int i = tid; i < 128 * 16; i += 256) {
        int r = i >> 4, c = i & 15;
        uint32_t so = (uint32_t)r * RST + c * 16;
        size_t go = (size_t)r * 256 + c * 16;
        cp16(sb + BO_BH + so, gb_h + go);
        cp16(sb + BO_BL + so, gb_l + go);
    }
    CP_WAIT_ALL();
    __syncthreads();

    // ldmatrix addresses
    const uint32_t m8 = lane >> 3, mr = lane & 7;
    const uint32_t aH0 = sb + BO_QH + (uint32_t)(32 * rg + ((m8 & 1) << 3) + mr) * RST
                       + (m8 >> 1) * 16;
    const uint32_t aL0 = aH0 + (BO_QL - BO_QH);
    const int nB = (int)((m8 >> 1) * 8 + mr);
    const uint32_t cBy = (m8 & 1) * 16;
    const uint32_t bA0 = sb + BO_BH + (uint32_t)(32 * nq + nB) * RST + cBy;      // n16 group 0
    const uint32_t bA1 = bA0 + 16 * RST;                                         // n16 group 1

    float acc[4][2][4];               // [n8 tile][m16 half][4]
    #pragma unroll
    for (int u = 0; u < 4; u++)
        #pragma unroll
        for (int mh = 0; mh < 2; mh++)
            #pragma unroll
            for (int e = 0; e < 4; e++) acc[u][mh][e] = 0.0f;

    #pragma unroll 1
    for (int kt = 0; kt < 8; kt++) {
        uint32_t ah0[4], ah1[4], al0[4], al1[4];
        ldsm4(ah0, aH0 + kt * 32);
        ldsm4(ah1, aH0 + 16 * RST + kt * 32);
        ldsm4(al0, aL0 + kt * 32);
        ldsm4(al1, aL0 + 16 * RST + kt * 32);
        uint32_t bh[4], bl[4];
        ldsm4(bh, bA0 + kt * 32);
        ldsm4(bl, bA0 + (BO_BL - BO_BH) + kt * 32);
        mma3(acc[0][0], ah0, al0, bh[0], bh[1], bl[0], bl[1]);
        mma3(acc[0][1], ah1, al1, bh[0], bh[1], bl[0], bl[1]);
        mma3(acc[1][0], ah0, al0, bh[2], bh[3], bl[2], bl[3]);
        mma3(acc[1][1], ah1, al1, bh[2], bh[3], bl[2], bl[3]);
        ldsm4(bh, bA1 + kt * 32);
        ldsm4(bl, bA1 + (BO_BL - BO_BH) + kt * 32);
        mma3(acc[2][0], ah0, al0, bh[0], bh[1], bl[0], bl[1]);
        mma3(acc[2][1], ah1, al1, bh[0], bh[1], bl[0], bl[1]);
        mma3(acc[3][0], ah0, al0, bh[2], bh[3], bl[2], bl[3]);
        mma3(acc[3][1], ah1, al1, bh[2], bh[3], bl[2], bl[3]);
    }

    // ---- RMW epilogue: Z += P ----
    float* __restrict__ Zb = Z + (size_t)m0 * Tz + n0;
    #pragma unroll
    for (int u = 0; u < 4; u++) {
        const int col = 32 * nq + u * 8 + lc;
        #pragma unroll
        for (int mh = 0; mh < 2; mh++)
            #pragma unroll
            for (int hh = 0; hh < 2; hh++) {
                const int row = 32 * rg + 16 * mh + 8 * hh + lr;
                float2* p = (float2*)(Zb + (size_t)row * Tz + col);
                float2 z = *p;
                z.x += acc[u][mh][2 * hh];
                z.y += acc[u][mh][2 * hh + 1];
                *p = z;
            }
    }
}

// ---------------------------------------------------------------------------
extern "C" void kernel_launch(void* const* d_in, const int* in_sizes, int n_in,
                              void* d_out, int out_size)
{
    const float* Q    = (const float*)d_in[0];   // (16, 1024, 128)
    const float* K    = (const float*)d_in[1];   // (16, 2047, 128)
    const float* bias = (const float*)d_in[2];   // (128, 1024)
    float* Z = (float*)d_out;                    // (16, 1024, 1024)

    static int configured = 0;
    if (!configured) {
        cudaFuncSetAttribute(band_kernel,
                             cudaFuncAttributeMaxDynamicSharedMemorySize, SMEM_BAND);
        cudaFuncSetAttribute(bias_kernel,
                             cudaFuncAttributeMaxDynamicSharedMemorySize, SMEM_BIAS);
        configured = 1;
    }

    conv_all_kernel<<<6270, 256>>>(Q, K, bias);

    dim3 bgrid(256, 4, 1);              // x = b*16 + w-strip, y = t-strip
    band_kernel<<<bgrid, 256, SMEM_BAND>>>(Z);

    dim3 pgrid(256, 8, 1);              // x = m-tile (64 rows), y = n-tile (128 cols)
    bias_kernel<<<pgrid, 256, SMEM_BIAS>>>(Z);
}

// round 9
// speedup vs baseline: 1.3851x; 1.0313x over previous
#include <cuda_runtime.h>
#include <cuda_bf16.h>
#include <stdint.h>

// SlidingWindowMatrixMult3D via mma.sync bf16, 3-pass fp32 emulation.
// Z[b,w,t] = sum_c Q[b,w,c]*K[b,w+t,c] + sum_c Q[b,w,c]*bias[c,t]
// B=16, T=1024, C=128.
//
// R9: R8 structure (conv pre-pass + band kernel + bias GEMM kernel), band
// kernel restructured: A fragments register-cached per kt-half, B fragments
// double-buffered (software pipeline) per n16 group. 2 CTA/SM everywhere.

#define Bz 16
#define Tz 1024
#define Cz 128
#define KTOT 2047
#define KPADROWS 128

// ---- global bf16 scratch ----
__device__ __nv_bfloat16 g_Qh[Bz * Tz * Cz];
__device__ __nv_bfloat16 g_Ql[Bz * Tz * Cz];
__device__ __nv_bfloat16 g_Kh[(Bz * KTOT + KPADROWS) * Cz];
__device__ __nv_bfloat16 g_Kl[(Bz * KTOT + KPADROWS) * Cz];
__device__ __nv_bfloat16 g_Bh[Tz * Cz];     // transposed: [t][c]
__device__ __nv_bfloat16 g_Bl[Tz * Cz];

// ---- shared layouts (both kernels 102 KB -> 2 CTA/SM) ----
#define RST 272u
#define OFF_QH 0u
#define OFF_QL 17408u
#define OFF_KH 34816u            // 128-slot ring (hi)
#define OFF_KL 69632u            // 128-slot ring (lo)
#define DHL    34816u            // hi -> lo delta
#define SMEM_BAND 104448u
#define BO_QH 0u
#define BO_QL 17408u
#define BO_BH 34816u
#define BO_BL 69632u
#define SMEM_BIAS 104448u

// ---------------------------------------------------------------------------
__device__ __forceinline__ uint32_t cvta_sh(const void* p) {
    uint32_t a;
    asm("{ .reg .u64 t; cvta.to.shared.u64 t, %1; cvt.u32.u64 %0, t; }"
        : "=r"(a) : "l"(p));
    return a;
}
__device__ __forceinline__ void cp16(uint32_t d, const void* s) {
    asm volatile("cp.async.ca.shared.global [%0], [%1], 16;" :: "r"(d), "l"(s));
}
#define CP_WAIT_ALL() asm volatile("cp.async.wait_all;" ::: "memory")

__device__ __forceinline__ void ldsm4(uint32_t* r, uint32_t a) {
    asm volatile("ldmatrix.sync.aligned.m8n8.x4.shared.b16 {%0,%1,%2,%3}, [%4];"
                 : "=r"(r[0]), "=r"(r[1]), "=r"(r[2]), "=r"(r[3]) : "r"(a));
}
__device__ __forceinline__ void ldsm2(uint32_t* r, uint32_t a) {
    asm volatile("ldmatrix.sync.aligned.m8n8.x2.shared.b16 {%0,%1}, [%2];"
                 : "=r"(r[0]), "=r"(r[1]) : "r"(a));
}
__device__ __forceinline__ void mma_bf16(float* d, const uint32_t* a,
                                         uint32_t b0, uint32_t b1) {
    asm volatile(
        "mma.sync.aligned.m16n8k16.row.col.f32.bf16.bf16.f32 "
        "{%0,%1,%2,%3}, {%4,%5,%6,%7}, {%8,%9}, {%0,%1,%2,%3};"
        : "+f"(d[0]), "+f"(d[1]), "+f"(d[2]), "+f"(d[3])
        : "r"(a[0]), "r"(a[1]), "r"(a[2]), "r"(a[3]), "r"(b0), "r"(b1));
}
__device__ __forceinline__ void mma3(float* d, const uint32_t* ah, const uint32_t* al,
                                     uint32_t bh0, uint32_t bh1,
                                     uint32_t bl0, uint32_t bl1) {
    mma_bf16(d, ah, bh0, bh1);
    mma_bf16(d, al, bh0, bh1);
    mma_bf16(d, ah, bl0, bl1);
}

// ---------------------------------------------------------------------------
// pre-pass: Q, K (float4 path) + bias transpose
__global__ void conv_all_kernel(const float* __restrict__ Q,
                                const float* __restrict__ K,
                                const float* __restrict__ bias)
{
    const int nQ = Bz * Tz * Cz / 4;        // 524288
    const int nK = Bz * KTOT * Cz / 4;      // 1048064
    const int nB = Tz * Cz / 4;             // 32768
    int i = blockIdx.x * blockDim.x + threadIdx.x;
    if (i < nQ + nK) {
        const float4* src;
        uint2 *dh, *dl;
        int j;
        if (i < nQ) { src = (const float4*)Q; dh = (uint2*)g_Qh; dl = (uint2*)g_Ql; j = i; }
        else        { src = (const float4*)K; dh = (uint2*)g_Kh; dl = (uint2*)g_Kl; j = i - nQ; }
        float4 v = __ldg(src + j);
        __nv_bfloat162 h01 = __floats2bfloat162_rn(v.x, v.y);
        __nv_bfloat162 h23 = __floats2bfloat162_rn(v.z, v.w);
        float2 f01 = __bfloat1622float2(h01);
        float2 f23 = __bfloat1622float2(h23);
        __nv_bfloat162 l01 = __floats2bfloat162_rn(v.x - f01.x, v.y - f01.y);
        __nv_bfloat162 l23 = __floats2bfloat162_rn(v.z - f23.x, v.w - f23.y);
        uint2 h, l;
        h.x = *(uint32_t*)&h01; h.y = *(uint32_t*)&h23;
        l.x = *(uint32_t*)&l01; l.y = *(uint32_t*)&l23;
        dh[j] = h;
        dl[j] = l;
    } else if (i < nQ + nK + nB) {
        int u = i - nQ - nK;
        int o = u * 4;
        int t = o >> 7, c = o & 127;
        float4 v;
        v.x = __ldg(bias + (c + 0) * Tz + t);
        v.y = __ldg(bias + (c + 1) * Tz + t);
        v.z = __ldg(bias + (c + 2) * Tz + t);
        v.w = __ldg(bias + (c + 3) * Tz + t);
        __nv_bfloat162 h01 = __floats2bfloat162_rn(v.x, v.y);
        __nv_bfloat162 h23 = __floats2bfloat162_rn(v.z, v.w);
        float2 f01 = __bfloat1622float2(h01);
        float2 f23 = __bfloat1622float2(h23);
        __nv_bfloat162 l01 = __floats2bfloat162_rn(v.x - f01.x, v.y - f01.y);
        __nv_bfloat162 l23 = __floats2bfloat162_rn(v.z - f23.x, v.w - f23.y);
        uint2 h, l;
        h.x = *(uint32_t*)&h01; h.y = *(uint32_t*)&h23;
        l.x = *(uint32_t*)&l01; l.y = *(uint32_t*)&l23;
        ((uint2*)g_Bh)[u] = h;
        ((uint2*)g_Bl)[u] = l;
    }
}

// ---------------------------------------------------------------------------
// Kernel 1: band term. 64w x 256t strips, sliding K ring, pure Z stores.
// A register-cached per kt-half; B double-buffered per n16 group.
__global__ void __launch_bounds__(256, 2)
band_kernel(float* __restrict__ Z)
{
    extern __shared__ char sm[];
    const uint32_t sb = cvta_sh(sm);

    const int tid  = threadIdx.x;
    const int wid  = tid >> 5;
    const int lane = tid & 31;
    const int lr = lane >> 2;
    const int lc = (lane & 3) * 2;
    const int mt = wid >> 1;
    const int s  = wid & 1;

    const int b  = blockIdx.x >> 4;
    const int w0 = (blockIdx.x & 15) * 64;
    const int t0 = blockIdx.y * 256;
    const int kbase = w0 + t0;

    const char* gq_h = (const char*)g_Qh + (size_t)(b * Tz + w0) * 256;
    const char* gq_l = (const char*)g_Ql + (size_t)(b * Tz + w0) * 256;
    const char* gk_h = (const char*)g_Kh + (size_t)(b * KTOT + kbase) * 256;
    const char* gk_l = (const char*)g_Kl + (size_t)(b * KTOT + kbase) * 256;

    // zero ring slot 127 (read via tile alignment on j=0, masked but must be finite)
    if (tid < 34) {
        uint32_t off = (tid < 17 ? OFF_KH : OFF_KL) + 127u * RST + (tid % 17) * 16;
        *(uint4*)(sm + off) = make_uint4(0, 0, 0, 0);
    }

    for (int i = tid; i < 64 * 16; i += 256) {
        int r = i >> 4, c = i & 15;
        uint32_t so = (uint32_t)r * RST + c * 16;
        size_t go = (size_t)r * 256 + c * 16;
        cp16(sb + OFF_QH + so, gq_h + go);
        cp16(sb + OFF_QL + so, gq_l + go);
    }
    for (int i = tid; i < 127 * 16; i += 256) {
        int r = i >> 4, c = i & 15;
        uint32_t so = (uint32_t)r * RST + c * 16;
        size_t go = (size_t)r * 256 + c * 16;
        cp16(sb + OFF_KH + so, gk_h + go);
        cp16(sb + OFF_KL + so, gk_l + go);
    }

    // ldmatrix lane components
    const uint32_t m8 = lane >> 3, mr = lane & 7;
    const uint32_t a_row = 16u * mt + ((m8 & 1) << 3) + mr;
    const uint32_t aH = sb + OFF_QH + a_row * RST + (m8 >> 1) * 16;
    const uint32_t aL = aH + (OFF_QL - OFF_QH);
    const int rB  = (int)((m8 >> 1) * 8 + mr);
    const uint32_t cB = (m8 & 1) * 16;
    const uint32_t l16 = lane & 15;
    const int rB2 = (int)(l16 & 7);
    const uint32_t cB2 = (l16 >> 3) * 16;

    const int gnt0 = 2 * mt + 5 * s;

    #pragma unroll 1
    for (int j = 0; j < 4; j++) {
        const int wb = 64 * j;
        float* __restrict__ Zb = Z + ((size_t)b * Tz + w0) * Tz + t0 + wb;

        CP_WAIT_ALL();
        __syncthreads();

        float acc[5][4];
        #pragma unroll
        for (int u = 0; u < 5; u++)
            #pragma unroll
            for (int e = 0; e < 4; e++) acc[u][e] = 0.0f;

        const uint32_t bb0 = sb + OFF_KH + (uint32_t)((wb + gnt0 * 8 + rB) & 127) * RST + cB;
        const uint32_t bb1 = sb + OFF_KH + (uint32_t)((wb + (gnt0 + 2) * 8 + rB) & 127) * RST + cB;
        const uint32_t bb2 = sb + OFF_KH + (uint32_t)((wb + (gnt0 + 4) * 8 + rB2) & 127) * RST + cB2;

        #pragma unroll
        for (int half = 0; half < 2; half++) {
            const uint32_t kb = (uint32_t)half * 128;    // 4 kt * 32B

            // A fragments for this half, register-cached
            uint32_t Ah[4][4], Al[4][4];
            #pragma unroll
            for (int q = 0; q < 4; q++) {
                ldsm4(Ah[q], aH + kb + q * 32);
                ldsm4(Al[q], aL + kb + q * 32);
            }

            // ---- group 0: n16 pair (gnt0, gnt0+1), B double-buffered ----
            {
                uint32_t bh[2][4], bl[2][4];
                ldsm4(bh[0], bb0 + kb);
                ldsm4(bl[0], bb0 + DHL + kb);
                #pragma unroll
                for (int q = 0; q < 4; q++) {
                    const int cur = q & 1, nxt = cur ^ 1;
                    if (q < 3) {
                        ldsm4(bh[nxt], bb0 + kb + (q + 1) * 32);
                        ldsm4(bl[nxt], bb0 + DHL + kb + (q + 1) * 32);
                    }
                    mma3(acc[0], Ah[q], Al[q], bh[cur][0], bh[cur][1], bl[cur][0], bl[cur][1]);
                    mma3(acc[1], Ah[q], Al[q], bh[cur][2], bh[cur][3], bl[cur][2], bl[cur][3]);
                }
            }
            // ---- group 1: n16 pair (gnt0+2, gnt0+3) ----
            {
                uint32_t bh[2][4], bl[2][4];
                ldsm4(bh[0], bb1 + kb);
                ldsm4(bl[0], bb1 + DHL + kb);
                #pragma unroll
                for (int q = 0; q < 4; q++) {
                    const int cur = q & 1, nxt = cur ^ 1;
                    if (q < 3) {
                        ldsm4(bh[nxt], bb1 + kb + (q + 1) * 32);
                        ldsm4(bl[nxt], bb1 + DHL + kb + (q + 1) * 32);
                    }
                    mma3(acc[2], Ah[q], Al[q], bh[cur][0], bh[cur][1], bl[cur][0], bl[cur][1]);
                    mma3(acc[3], Ah[q], Al[q], bh[cur][2], bh[cur][3], bl[cur][2], bl[cur][3]);
                }
            }
            // ---- group 2: lone n8 tile (gnt0+4) via ldsm2 ----
            {
                uint32_t bh[2][2], bl[2][2];
                ldsm2(bh[0], bb2 + kb);
                ldsm2(bl[0], bb2 + DHL + kb);
                #pragma unroll
                for (int q = 0; q < 4; q++) {
                    const int cur = q & 1, nxt = cur ^ 1;
                    if (q < 3) {
                        ldsm2(bh[nxt], bb2 + kb + (q + 1) * 32);
                        ldsm2(bl[nxt], bb2 + DHL + kb + (q + 1) * 32);
                    }
                    mma3(acc[4], Ah[q], Al[q], bh[cur][0], bh[cur][1], bl[cur][0], bl[cur][1]);
                }
            }
        }
        __syncthreads();                         // all ring reads complete

        // ---- prefetch next 64 K rows (rel [wb+127, wb+190]) ----
        if (j < 3) {
            for (int i = tid; i < 64 * 16; i += 256) {
                int r = i >> 4, c = i & 15;
                int rel = wb + 127 + r;
                uint32_t so = (uint32_t)(rel & 127) * RST + c * 16;
                size_t go = (size_t)rel * 256 + c * 16;
                cp16(sb + OFF_KH + so, gk_h + go);
                cp16(sb + OFF_KL + so, gk_l + go);
            }
        }

        // ---- scatter band sheared to Z (pure store; overlaps prefetch) ----
        #pragma unroll
        for (int u = 0; u < 5; u++) {
            const int n0 = (gnt0 + u) * 8 + lc;
            #pragma unroll
            for (int h = 0; h < 2; h++) {
                const int row = 16 * mt + lr + 8 * h;
                const int j0 = n0 - row;
                if ((unsigned)j0 < 64u)       Zb[(size_t)row * Tz + j0]     = acc[u][2 * h];
                if ((unsigned)(j0 + 1) < 64u) Zb[(size_t)row * Tz + j0 + 1] = acc[u][2 * h + 1];
            }
        }
    }
}

// ---------------------------------------------------------------------------
// Kernel 2: bias GEMM, Z += Q @ bias^T. 64m x 128n tiles, m32n32 warps.
__global__ void __launch_bounds__(256, 2)
bias_kernel(float* __restrict__ Z)
{
    extern __shared__ char sm[];
    const uint32_t sb = cvta_sh(sm);

    const int tid  = threadIdx.x;
    const int wid  = tid >> 5;
    const int lane = tid & 31;
    const int lr = lane >> 2;
    const int lc = (lane & 3) * 2;
    const int rg = wid & 1;
    const int nq = wid >> 1;

    const int m0 = blockIdx.x * 64;
    const int n0 = blockIdx.y * 128;

    const char* gq_h = (const char*)g_Qh + (size_t)m0 * 256;
    const char* gq_l = (const char*)g_Ql + (size_t)m0 * 256;
    const char* gb_h = (const char*)g_Bh + (size_t)n0 * 256;
    const char* gb_l = (const char*)g_Bl + (size_t)n0 * 256;

    for (int i = tid; i < 64 * 16; i += 256) {
        int r = i >> 4, c = i & 15;
        uint32_t so = (uint32_t)r * RST + c * 16;
        size_t go = (size_t)r * 256 + c * 16;
        cp16(sb + BO_QH + so, gq_h + go);
        cp16(sb + BO_QL + so, gq_l + go);
    }
    for (int i = tid; i < 128 * 16; i += 256) {
        int r = i >> 4, c = i & 15;
        uint32_t so = (uint32_t)r * RST + c * 16;
        size_t go = (size_t)r * 256 + c * 16;
        cp16(sb + BO_BH + so, gb_h + go);
        cp16(sb + BO_BL + so, gb_l + go);
    }
    CP_WAIT_ALL();
    __syncthreads();

    const uint32_t m8 = lane >> 3, mr = lane & 7;
    const uint32_t aH0 = sb + BO_QH + (uint32_t)(32 * rg + ((m8 & 1) << 3) + mr) * RST
                       + (m8 >> 1) * 16;
    const uint32_t aL0 = aH0 + (BO_QL - BO_QH);
    const int nB = (int)((m8 >> 1) * 8 + mr);
    const uint32_t cBy = (m8 & 1) * 16;
    const uint32_t bA0 = sb + BO_BH + (uint32_t)(32 * nq + nB) * RST + cBy;
    const uint32_t bA1 = bA0 + 16 * RST;

    float acc[4][2][4];
    #pragma unroll
    for (int u = 0; u < 4; u++)
        #pragma unroll
        for (int mh = 0; mh < 2; mh++)
            #pragma unroll
            for (int e = 0; e < 4; e++) acc[u][mh][e] = 0.0f;

    #pragma unroll 1
    for (int kt = 0; kt < 8; kt++) {
        uint32_t ah0[4], ah1[4], al0[4], al1[4];
        ldsm4(ah0, aH0 + kt * 32);
        ldsm4(ah1, aH0 + 16 * RST + kt * 32);
        ldsm4(al0, aL0 + kt * 32);
        ldsm4(al1, aL0 + 16 * RST + kt * 32);
        uint32_t bh[4], bl[4];
        ldsm4(bh, bA0 + kt * 32);
        ldsm4(bl, bA0 + (BO_BL - BO_BH) + kt * 32);
        mma3(acc[0][0], ah0, al0, bh[0], bh[1], bl[0], bl[1]);
        mma3(acc[0][1], ah1, al1, bh[0], bh[1], bl[0], bl[1]);
        mma3(acc[1][0], ah0, al0, bh[2], bh[3], bl[2], bl[3]);
        mma3(acc[1][1], ah1, al1, bh[2], bh[3], bl[2], bl[3]);
        ldsm4(bh, bA1 + kt * 32);
        ldsm4(bl, bA1 + (BO_BL - BO_BH) + kt * 32);
        mma3(acc[2][0], ah0, al0, bh[0], bh[1], bl[0], bl[1]);
        mma3(acc[2][1], ah1, al1, bh[0], bh[1], bl[0], bl[1]);
        mma3(acc[3][0], ah0, al0, bh[2], bh[3], bl[2], bl[3]);
        mma3(acc[3][1], ah1, al1, bh[2], bh[3], bl[2], bl[3]);
    }

    float* __restrict__ Zb = Z + (size_t)m0 * Tz + n0;
    #pragma unroll
    for (int u = 0; u < 4; u++) {
        const int col = 32 * nq + u * 8 + lc;
        #pragma unroll
        for (int mh = 0; mh < 2; mh++)
            #pragma unroll
            for (int hh = 0; hh < 2; hh++) {
                const int row = 32 * rg + 16 * mh + 8 * hh + lr;
                float2* p = (float2*)(Zb + (size_t)row * Tz + col);
                float2 z = *p;
                z.x += acc[u][mh][2 * hh];
                z.y += acc[u][mh][2 * hh + 1];
                *p = z;
            }
    }
}

// ---------------------------------------------------------------------------
extern "C" void kernel_launch(void* const* d_in, const int* in_sizes, int n_in,
                              void* d_out, int out_size)
{
    const float* Q    = (const float*)d_in[0];   // (16, 1024, 128)
    const float* K    = (const float*)d_in[1];   // (16, 2047, 128)
    const float* bias = (const float*)d_in[2];   // (128, 1024)
    float* Z = (float*)d_out;                    // (16, 1024, 1024)

    static int configured = 0;
    if (!configured) {
        cudaFuncSetAttribute(band_kernel,
                             cudaFuncAttributeMaxDynamicSharedMemorySize, SMEM_BAND);
        cudaFuncSetAttribute(bias_kernel,
                             cudaFuncAttributeMaxDynamicSharedMemorySize, SMEM_BIAS);
        configured = 1;
    }

    conv_all_kernel<<<6270, 256>>>(Q, K, bias);

    dim3 bgrid(256, 4, 1);              // x = b*16 + w-strip, y = t-strip
    band_kernel<<<bgrid, 256, SMEM_BAND>>>(Z);

    dim3 pgrid(256, 8, 1);              // x = m-tile (64 rows), y = n-tile (128 cols)
    bias_kernel<<<pgrid, 256, SMEM_BIAS>>>(Z);
}